// round 5
// baseline (speedup 1.0000x reference)
#include <cuda_runtime.h>
#include <math.h>

// Problem: D [n, 512] fp32 row-major.
//   diag[j]  = sum_i D[i][j]^2
//   out      = 0.001 * sqrt( sum_j (diag[j]-1)^2 )
//
// Pass 1: column-squared-norm partials per block (HBM streaming, LDG.128).
// Pass 2: reduce partials across blocks, residual^2 sum, sqrt, scale.

#define D_COLS 512
#define NB     1024          // pass-1 grid size
#define TPB    256           // 128 threads per row, 2 rows per iteration

// Per-block partial column sums: NB x 512 floats = 2 MB static device scratch.
__device__ float g_partials[NB * D_COLS];

__global__ void __launch_bounds__(TPB, 4)
colsq_partial_kernel(const float* __restrict__ D, int n) {
    const int tid  = threadIdx.x;
    const int c4   = tid & 127;        // which float4 within the 512-col row
    const int rsub = tid >> 7;         // 0 or 1: which of the block's 2 rows
    const float4* __restrict__ Dv = (const float4*)D;

    float a0 = 0.f, a1 = 0.f, a2 = 0.f, a3 = 0.f;

    const int stride = NB * 2;         // rows advanced per grid iteration
    int row = blockIdx.x * 2 + rsub;

    // n = 262144, stride = 2048 -> exactly 128 iterations per thread.
    #pragma unroll 8
    for (; row < n; row += stride) {
        float4 v = Dv[(size_t)row * 128 + c4];
        a0 = fmaf(v.x, v.x, a0);
        a1 = fmaf(v.y, v.y, a1);
        a2 = fmaf(v.z, v.z, a2);
        a3 = fmaf(v.w, v.w, a3);
    }

    // Combine the two row-halves of the block, write 512 partials per block.
    __shared__ float4 s[TPB];
    s[tid] = make_float4(a0, a1, a2, a3);
    __syncthreads();

    if (tid < 128) {
        float4 lo = s[tid];
        float4 hi = s[tid + 128];
        float4 r = make_float4(lo.x + hi.x, lo.y + hi.y, lo.z + hi.z, lo.w + hi.w);
        ((float4*)(g_partials + (size_t)blockIdx.x * D_COLS))[c4] = r;
    }
}

__global__ void __launch_bounds__(D_COLS)
finalize_kernel(float* __restrict__ out) {
    const int j = threadIdx.x;         // column index, 512 threads

    // Sum the NB block partials for this column (coalesced across threads).
    double s = 0.0;
    #pragma unroll 8
    for (int b = 0; b < NB; b++)
        s += (double)g_partials[(size_t)b * D_COLS + j];

    double r = s - 1.0;
    double r2 = r * r;

    __shared__ double sh[D_COLS];
    sh[j] = r2;
    __syncthreads();
    #pragma unroll
    for (int off = D_COLS / 2; off > 0; off >>= 1) {
        if (j < off) sh[j] += sh[j + off];
        __syncthreads();
    }

    if (j == 0)
        out[0] = (float)(0.001 * sqrt(sh[0]));
}

extern "C" void kernel_launch(void* const* d_in, const int* in_sizes, int n_in,
                              void* d_out, int out_size) {
    const float* D = (const float*)d_in[0];
    const int n = in_sizes[0] / D_COLS;     // rows
    float* out = (float*)d_out;

    colsq_partial_kernel<<<NB, TPB>>>(D, n);
    finalize_kernel<<<1, D_COLS>>>(out);
}

// round 10
// speedup vs baseline: 3.8885x; 3.8885x over previous
#include <cuda_runtime.h>
#include <math.h>

// Problem: D [n, 512] fp32 row-major.
//   diag[j]  = sum_i D[i][j]^2
//   out      = 0.001 * sqrt( sum_j (diag[j]-1)^2 )
//
// Pass 1: per-block partial column squared-norms (HBM streaming, LDG.128). ~79us (roofline).
// Pass 2: parallel cross-block column reduction, 1024 -> 8 partials/col.     ~3us
// Pass 3: tiny epilogue: 8 -> 1 per col, residual^2, norm, sqrt, scale.      ~2us

#define D_COLS 512
#define NB     1024          // pass-1 grid size
#define TPB    256           // 128 threads per row, 2 rows per iteration
#define NB2    8             // pass-2 grid size (stage-2 partials per column)

// Per-block partial column sums: NB x 512 floats = 2 MB static device scratch.
__device__ float g_partials[NB * D_COLS];
// Stage-2 partials: 8 x 512 floats.
__device__ float g_stage2[NB2 * D_COLS];

__global__ void __launch_bounds__(TPB, 4)
colsq_partial_kernel(const float* __restrict__ D, int n) {
    const int tid  = threadIdx.x;
    const int c4   = tid & 127;        // which float4 within the 512-col row
    const int rsub = tid >> 7;         // 0 or 1: which of the block's 2 rows
    const float4* __restrict__ Dv = (const float4*)D;

    float a0 = 0.f, a1 = 0.f, a2 = 0.f, a3 = 0.f;

    const int stride = NB * 2;         // rows advanced per grid iteration
    int row = blockIdx.x * 2 + rsub;

    // n = 262144, stride = 2048 -> exactly 128 iterations per thread.
    #pragma unroll 8
    for (; row < n; row += stride) {
        float4 v = Dv[(size_t)row * 128 + c4];
        a0 = fmaf(v.x, v.x, a0);
        a1 = fmaf(v.y, v.y, a1);
        a2 = fmaf(v.z, v.z, a2);
        a3 = fmaf(v.w, v.w, a3);
    }

    // Combine the two row-halves of the block, write 512 partials per block.
    __shared__ float4 s[TPB];
    s[tid] = make_float4(a0, a1, a2, a3);
    __syncthreads();

    if (tid < 128) {
        float4 lo = s[tid];
        float4 hi = s[tid + 128];
        float4 r = make_float4(lo.x + hi.x, lo.y + hi.y, lo.z + hi.z, lo.w + hi.w);
        ((float4*)(g_partials + (size_t)blockIdx.x * D_COLS))[c4] = r;
    }
}

// Pass 2: each of 8 blocks sums 128 of the 1024 partial rows for all 512
// columns. Thread j handles column j -> fully coalesced loads; 8 independent
// fp32 accumulators break the dependency chain and give ptxas a deep
// front-batched LDG window (MLP ~16) to hide L2 latency.
__global__ void __launch_bounds__(D_COLS)
reduce_partials_kernel(void) {
    const int j = threadIdx.x;                       // column
    const int base = blockIdx.x * (NB / NB2);        // 128 rows per block

    float a[8] = {0.f, 0.f, 0.f, 0.f, 0.f, 0.f, 0.f, 0.f};
    #pragma unroll 2
    for (int i = 0; i < NB / NB2; i += 8) {
        #pragma unroll
        for (int k = 0; k < 8; k++)
            a[k] += g_partials[(size_t)(base + i + k) * D_COLS + j];
    }
    float r = ((a[0] + a[1]) + (a[2] + a[3])) + ((a[4] + a[5]) + (a[6] + a[7]));
    g_stage2[(size_t)blockIdx.x * D_COLS + j] = r;
}

// Pass 3: finish. 8 adds per column, residual^2, block tree-reduce, output.
__global__ void __launch_bounds__(D_COLS)
finalize_kernel(float* __restrict__ out) {
    const int j = threadIdx.x;

    float diag = 0.f;
    #pragma unroll
    for (int b = 0; b < NB2; b++)
        diag += g_stage2[(size_t)b * D_COLS + j];

    double r = (double)diag - 1.0;
    double r2 = r * r;

    __shared__ double sh[D_COLS];
    sh[j] = r2;
    __syncthreads();
    #pragma unroll
    for (int off = D_COLS / 2; off > 0; off >>= 1) {
        if (j < off) sh[j] += sh[j + off];
        __syncthreads();
    }

    if (j == 0)
        out[0] = (float)(0.001 * sqrt(sh[0]));
}

extern "C" void kernel_launch(void* const* d_in, const int* in_sizes, int n_in,
                              void* d_out, int out_size) {
    const float* D = (const float*)d_in[0];
    const int n = in_sizes[0] / D_COLS;     // rows
    float* out = (float*)d_out;

    colsq_partial_kernel<<<NB, TPB>>>(D, n);
    reduce_partials_kernel<<<NB2, D_COLS>>>();
    finalize_kernel<<<1, D_COLS>>>(out);
}

// round 13
// speedup vs baseline: 4.2342x; 1.0889x over previous
#include <cuda_runtime.h>
#include <math.h>

// Problem: D [n, 512] fp32 row-major.
//   diag[j]  = sum_i D[i][j]^2
//   out      = 0.001 * sqrt( sum_j (diag[j]-1)^2 )
//
// Pass 1: per-block partial column squared-norms, single wave (592 CTAs).   ~78us (HBM roofline)
// Pass 2 (fused): cross-block column reduction + last-block finalize.        ~3-4us

#define D_COLS 512
#define NB     592           // pass-1 grid: 148 SMs x 4 CTAs = exactly one wave
#define TPB    256           // 128 threads per row, 2 rows per block-iteration
#define NB2    16            // fused-pass grid
#define ROWS_PER_B2 (NB / NB2)   // 37 partial rows per pass-2 block

// Per-block partial column sums: NB x 512 floats (~1.2 MB) static scratch.
__device__ float g_partials[NB * D_COLS];
// Stage-2 partials: NB2 x 512 floats.
__device__ float g_stage2[NB2 * D_COLS];
// Ticket counter for last-block election. Zero at load; reset each run.
__device__ unsigned int g_ticket;

__global__ void __launch_bounds__(TPB, 4)
colsq_partial_kernel(const float* __restrict__ D, int n) {
    const int tid  = threadIdx.x;
    const int c4   = tid & 127;        // which float4 within the 512-col row
    const int rsub = tid >> 7;         // 0 or 1: which of the block's 2 rows
    const float4* __restrict__ Dv = (const float4*)D;

    float a0 = 0.f, a1 = 0.f, a2 = 0.f, a3 = 0.f;

    const int stride = NB * 2;         // rows advanced per grid iteration
    int row = blockIdx.x * 2 + rsub;

    #pragma unroll 8
    for (; row < n; row += stride) {
        float4 v = Dv[(size_t)row * 128 + c4];
        a0 = fmaf(v.x, v.x, a0);
        a1 = fmaf(v.y, v.y, a1);
        a2 = fmaf(v.z, v.z, a2);
        a3 = fmaf(v.w, v.w, a3);
    }

    __shared__ float4 s[TPB];
    s[tid] = make_float4(a0, a1, a2, a3);
    __syncthreads();

    if (tid < 128) {
        float4 lo = s[tid];
        float4 hi = s[tid + 128];
        float4 r = make_float4(lo.x + hi.x, lo.y + hi.y, lo.z + hi.z, lo.w + hi.w);
        ((float4*)(g_partials + (size_t)blockIdx.x * D_COLS))[c4] = r;
    }
}

// Fused pass 2+3: 16 blocks each reduce 37 partial rows per column (coalesced,
// 4 independent accumulators), then the last block to finish sums the 16
// stage-2 rows, squares residuals, tree-reduces in double, writes the result,
// and resets the ticket for the next graph replay.
__global__ void __launch_bounds__(D_COLS)
reduce_finalize_kernel(float* __restrict__ out) {
    const int j = threadIdx.x;                       // column
    const int base = blockIdx.x * ROWS_PER_B2;

    float a[4] = {0.f, 0.f, 0.f, 0.f};
    #pragma unroll
    for (int i = 0; i < ROWS_PER_B2; i++)
        a[i & 3] += g_partials[(size_t)(base + i) * D_COLS + j];
    g_stage2[(size_t)blockIdx.x * D_COLS + j] = (a[0] + a[1]) + (a[2] + a[3]);

    // Make this thread's stage2 store visible device-wide, then elect last block.
    __threadfence();
    __shared__ unsigned int s_last;
    __syncthreads();                                 // all fences in block done
    if (j == 0) {
        unsigned int t = atomicAdd(&g_ticket, 1u);
        s_last = (t == (unsigned int)(gridDim.x - 1)) ? 1u : 0u;
    }
    __syncthreads();
    if (!s_last) return;

    // Last block: finish the reduction. __ldcg bypasses L1 (stage2 written by
    // other SMs; data is guaranteed in L2 by the fence/ticket ordering).
    float diag = 0.f;
    #pragma unroll
    for (int b = 0; b < NB2; b++)
        diag += __ldcg(&g_stage2[(size_t)b * D_COLS + j]);

    double r = (double)diag - 1.0;
    __shared__ double sh[D_COLS];
    sh[j] = r * r;
    __syncthreads();
    #pragma unroll
    for (int off = D_COLS / 2; off > 0; off >>= 1) {
        if (j < off) sh[j] += sh[j + off];
        __syncthreads();
    }

    if (j == 0) {
        out[0] = (float)(0.001 * sqrt(sh[0]));
        g_ticket = 0u;                               // reset for next replay
    }
}

extern "C" void kernel_launch(void* const* d_in, const int* in_sizes, int n_in,
                              void* d_out, int out_size) {
    const float* D = (const float*)d_in[0];
    const int n = in_sizes[0] / D_COLS;     // rows
    float* out = (float*)d_out;

    colsq_partial_kernel<<<NB, TPB>>>(D, n);
    reduce_finalize_kernel<<<NB2, D_COLS>>>(out);
}

// round 14
// speedup vs baseline: 4.2542x; 1.0047x over previous
#include <cuda_runtime.h>
#include <math.h>

// Problem: D [n, 512] fp32 row-major.
//   diag[j]  = sum_i D[i][j]^2
//   out      = 0.001 * sqrt( sum_j (diag[j]-1)^2 )
//
// Pass 1: per-block partial column squared-norms, single wave (592 CTAs).   ~78.6us (86.8% DRAM)
// Pass 2 (fused): cross-block column reduction + last-block finalize.
//   R13 measured 10us: partials re-read from DRAM (~600cyc) with MLP~4 on 16 SMs.
//   Now: 37 blocks x 16 rows, 8 accumulators fully unrolled (MLP 16/thread).

#define D_COLS 512
#define NB     592           // pass-1 grid: 148 SMs x 4 CTAs = exactly one wave
#define TPB    256           // 128 threads per row, 2 rows per block-iteration
#define NB2    37            // fused-pass grid
#define ROWS_PER_B2 (NB / NB2)   // 16 partial rows per pass-2 block

// Per-block partial column sums: NB x 512 floats (~1.2 MB) static scratch.
__device__ float g_partials[NB * D_COLS];
// Stage-2 partials: NB2 x 512 floats.
__device__ float g_stage2[NB2 * D_COLS];
// Ticket counter for last-block election. Zero at load; reset each run.
__device__ unsigned int g_ticket;

__global__ void __launch_bounds__(TPB, 4)
colsq_partial_kernel(const float* __restrict__ D, int n) {
    const int tid  = threadIdx.x;
    const int c4   = tid & 127;        // which float4 within the 512-col row
    const int rsub = tid >> 7;         // 0 or 1: which of the block's 2 rows
    const float4* __restrict__ Dv = (const float4*)D;

    float a0 = 0.f, a1 = 0.f, a2 = 0.f, a3 = 0.f;

    const int stride = NB * 2;         // rows advanced per grid iteration
    int row = blockIdx.x * 2 + rsub;

    #pragma unroll 8
    for (; row < n; row += stride) {
        float4 v = Dv[(size_t)row * 128 + c4];
        a0 = fmaf(v.x, v.x, a0);
        a1 = fmaf(v.y, v.y, a1);
        a2 = fmaf(v.z, v.z, a2);
        a3 = fmaf(v.w, v.w, a3);
    }

    __shared__ float4 s[TPB];
    s[tid] = make_float4(a0, a1, a2, a3);
    __syncthreads();

    if (tid < 128) {
        float4 lo = s[tid];
        float4 hi = s[tid + 128];
        float4 r = make_float4(lo.x + hi.x, lo.y + hi.y, lo.z + hi.z, lo.w + hi.w);
        ((float4*)(g_partials + (size_t)blockIdx.x * D_COLS))[c4] = r;
    }
}

// Fused pass 2+3: 37 blocks each reduce 16 partial rows per column with 8
// independent accumulators, fully unrolled -> 16 loads in flight to cover
// DRAM latency. Last block to finish sums the 37 stage-2 rows (L2-hot),
// squares residuals, tree-reduces in double, writes the result, resets ticket.
__global__ void __launch_bounds__(D_COLS)
reduce_finalize_kernel(float* __restrict__ out) {
    const int j = threadIdx.x;                       // column
    const size_t base = (size_t)blockIdx.x * ROWS_PER_B2 * D_COLS + j;

    float a[8] = {0.f, 0.f, 0.f, 0.f, 0.f, 0.f, 0.f, 0.f};
    #pragma unroll
    for (int i = 0; i < ROWS_PER_B2; i++)
        a[i & 7] += g_partials[base + (size_t)i * D_COLS];
    float r = ((a[0] + a[1]) + (a[2] + a[3])) + ((a[4] + a[5]) + (a[6] + a[7]));
    g_stage2[(size_t)blockIdx.x * D_COLS + j] = r;

    // Make this thread's stage2 store visible device-wide, then elect last block.
    __threadfence();
    __shared__ unsigned int s_last;
    __syncthreads();                                 // all fences in block done
    if (j == 0) {
        unsigned int t = atomicAdd(&g_ticket, 1u);
        s_last = (t == (unsigned int)(gridDim.x - 1)) ? 1u : 0u;
    }
    __syncthreads();
    if (!s_last) return;

    // Last block: finish. __ldcg bypasses L1 (stage2 written by other SMs;
    // guaranteed visible in L2 by the fence/ticket ordering). 8 independent
    // accumulators over 37 rows.
    float b[8] = {0.f, 0.f, 0.f, 0.f, 0.f, 0.f, 0.f, 0.f};
    #pragma unroll
    for (int k = 0; k < NB2; k++)
        b[k & 7] += __ldcg(&g_stage2[(size_t)k * D_COLS + j]);
    float diag = ((b[0] + b[1]) + (b[2] + b[3])) + ((b[4] + b[5]) + (b[6] + b[7]));

    double rr = (double)diag - 1.0;
    __shared__ double sh[D_COLS];
    sh[j] = rr * rr;
    __syncthreads();
    #pragma unroll
    for (int off = D_COLS / 2; off > 0; off >>= 1) {
        if (j < off) sh[j] += sh[j + off];
        __syncthreads();
    }

    if (j == 0) {
        out[0] = (float)(0.001 * sqrt(sh[0]));
        g_ticket = 0u;                               // reset for next replay
    }
}

extern "C" void kernel_launch(void* const* d_in, const int* in_sizes, int n_in,
                              void* d_out, int out_size) {
    const float* D = (const float*)d_in[0];
    const int n = in_sizes[0] / D_COLS;     // rows
    float* out = (float*)d_out;

    colsq_partial_kernel<<<NB, TPB>>>(D, n);
    reduce_finalize_kernel<<<NB2, D_COLS>>>(out);
}